// round 17
// baseline (speedup 1.0000x reference)
#include <cuda_runtime.h>

// RelationAwareAttention: B=1, H=8, L=512, D=64
// out = concat(attn_sum[1,8,512,64], p_attn[1,8,512,512]) as float32.
//
// Single fused launch, CTA-role specialization:
//   bids [0,512):    QK role — S1 = Q K^T (FFMA2 GEMM) -> g_s1, then signal.
//   bids [512,4608): stream role — phase 1 rk stream (no S1 needed), spin-wait
//                    on the QK signal, s1-add + softmax + p_attn + fused PV.
// QK (~8us) hides entirely under the stream CTAs' phase 1.

#define L_SEQ 512
#define D_DIM 64
#define H_HEADS 8
#define N_QK_CTAS 512
#define N_STREAM_CTAS (L_SEQ * H_HEADS)

__device__ float g_s1[(size_t)H_HEADS * L_SEQ * L_SEQ];   // 8.4 MB scratch
__device__ unsigned int g_a_done = 0;   // QK CTAs arrived
__device__ unsigned int g_b_done = 0;   // stream CTAs finished (for reset)

__device__ __forceinline__ unsigned long long pack2(float lo, float hi) {
    unsigned long long r;
    asm("mov.b64 %0, {%1, %2};" : "=l"(r) : "f"(lo), "f"(hi));
    return r;
}
__device__ __forceinline__ void unpack2(unsigned long long p, float& lo, float& hi) {
    asm("mov.b64 {%0, %1}, %2;" : "=f"(lo), "=f"(hi) : "l"(p));
}
__device__ __forceinline__ void fma2(unsigned long long& d,
                                     unsigned long long a, unsigned long long b) {
    asm("fma.rn.f32x2 %0, %1, %2, %0;" : "+l"(d) : "l"(a), "l"(b));
}

union SmemU {
    struct {                       // QK role
        float sqT[64][68];
        float skT[64][68];
    } a;
    struct {                       // stream role
        float  score[L_SEQ];
        int    mask[L_SEQ];
        float  red[8];
        float4 acc[16][16];
    } b;
};

__global__ __launch_bounds__(256, 6)
void fused_kernel(const float* __restrict__ q_g,
                  const float* __restrict__ k_g,
                  const float* __restrict__ v_g,
                  const float* __restrict__ rk_g,
                  const float* __restrict__ rv_g,
                  const int*   __restrict__ mask_g,
                  float* __restrict__ out_attn,
                  float* __restrict__ out_p)
{
    __shared__ SmemU sm;
    const int bid = blockIdx.x;
    const int tid = threadIdx.x;

    if (bid < N_QK_CTAS) {
        // ================= QK role: S1 = Q K^T (FFMA2) =================
        const int jt = bid & 7;            // 8
        const int it = (bid >> 3) & 7;     // 8
        const int h  = bid >> 6;           // 8
        const int i0 = it << 6, j0 = jt << 6;

        for (int idx = tid; idx < 64 * 16; idx += 256) {
            const int row = idx >> 4, c4 = (idx & 15) << 2;
            const float4 a = *reinterpret_cast<const float4*>(
                q_g + ((size_t)h * L_SEQ + i0 + row) * D_DIM + c4);
            sm.a.sqT[c4 + 0][row] = a.x; sm.a.sqT[c4 + 1][row] = a.y;
            sm.a.sqT[c4 + 2][row] = a.z; sm.a.sqT[c4 + 3][row] = a.w;
            const float4 b = *reinterpret_cast<const float4*>(
                k_g + ((size_t)h * L_SEQ + j0 + row) * D_DIM + c4);
            sm.a.skT[c4 + 0][row] = b.x; sm.a.skT[c4 + 1][row] = b.y;
            sm.a.skT[c4 + 2][row] = b.z; sm.a.skT[c4 + 3][row] = b.w;
        }
        __syncthreads();

        const int ty = tid >> 4, tx = tid & 15;   // 16x16 threads, 4x4 outputs
        unsigned long long acc01[4] = {0ull, 0ull, 0ull, 0ull};
        unsigned long long acc23[4] = {0ull, 0ull, 0ull, 0ull};

        #pragma unroll 8
        for (int kk = 0; kk < 64; ++kk) {
            const float4 av = *reinterpret_cast<const float4*>(&sm.a.sqT[kk][4 * ty]);
            const float4 bv = *reinterpret_cast<const float4*>(&sm.a.skT[kk][4 * tx]);
            const unsigned long long b01 = pack2(bv.x, bv.y);
            const unsigned long long b23 = pack2(bv.z, bv.w);
            const unsigned long long a0 = pack2(av.x, av.x);
            const unsigned long long a1 = pack2(av.y, av.y);
            const unsigned long long a2 = pack2(av.z, av.z);
            const unsigned long long a3 = pack2(av.w, av.w);
            fma2(acc01[0], a0, b01); fma2(acc23[0], a0, b23);
            fma2(acc01[1], a1, b01); fma2(acc23[1], a1, b23);
            fma2(acc01[2], a2, b01); fma2(acc23[2], a2, b23);
            fma2(acc01[3], a3, b01); fma2(acc23[3], a3, b23);
        }

        #pragma unroll
        for (int r = 0; r < 4; ++r) {
            float4 o;
            unpack2(acc01[r], o.x, o.y);
            unpack2(acc23[r], o.z, o.w);
            *reinterpret_cast<float4*>(
                g_s1 + ((size_t)h * L_SEQ + i0 + 4 * ty + r) * L_SEQ + j0 + 4 * tx) = o;
        }

        // Signal S1 tile complete (all stores visible first).
        __threadfence();
        __syncthreads();
        if (tid == 0) atomicAdd(&g_a_done, 1u);
        return;
    }

    // ================= stream role =================
    const int sb   = bid - N_QK_CTAS;
    const int i    = sb & (L_SEQ - 1);
    const int h    = sb >> 9;
    const int warp = tid >> 5;
    const int lane = tid & 31;
    const int half = lane >> 4;
    const int hl   = lane & 15;

    const float* q     = q_g  + ((size_t)h * L_SEQ + i) * D_DIM;
    const float* rk    = rk_g + (((size_t)h * L_SEQ + i) * L_SEQ) * D_DIM;
    const int*   mrow  = mask_g + (size_t)i * L_SEQ;          // broadcast over h (B=1)
    const float* s1row = g_s1 + ((size_t)h * L_SEQ + i) * L_SEQ;

    // Prologue: mask row into smem.
    sm.b.mask[tid]       = mrow[tid];
    sm.b.mask[tid + 256] = mrow[tid + 256];

    // Phase 1: raw dot p[j] = q . rk[i,j]  (no S1 needed — overlaps QK CTAs).
    const float4 q4 = *reinterpret_cast<const float4*>(q + 4 * hl);

    #pragma unroll 8
    for (int jj = 0; jj < 32; ++jj) {
        const int j = (warp << 6) + (jj << 1) + half;
        const float4 rr = __ldcs(reinterpret_cast<const float4*>(rk + (size_t)j * D_DIM + 4 * hl));
        float p = q4.x * rr.x + q4.y * rr.y + q4.z * rr.z + q4.w * rr.w;
        p += __shfl_xor_sync(0xffffffffu, p, 8);
        p += __shfl_xor_sync(0xffffffffu, p, 4);
        p += __shfl_xor_sync(0xffffffffu, p, 2);
        p += __shfl_xor_sync(0xffffffffu, p, 1);
        if (hl == 0) sm.b.score[j] = p;
    }
    __syncthreads();

    // Wait until all 512 QK CTAs have published their S1 tiles.
    if (tid == 0) {
        unsigned int v;
        do {
            asm volatile("ld.acquire.gpu.u32 %0, [%1];" : "=r"(v) : "l"(&g_a_done));
        } while (v < N_QK_CTAS);
    }
    __syncthreads();

    float v0 = (sm.b.score[tid]       + s1row[tid])       * 0.125f;   // 1/sqrt(64)
    float v1 = (sm.b.score[tid + 256] + s1row[tid + 256]) * 0.125f;
    if (sm.b.mask[tid] == 0)       v0 = -1e9f;
    if (sm.b.mask[tid + 256] == 0) v1 = -1e9f;

    // Phase 2: softmax over j (thread owns tid, tid+256).
    float m = fmaxf(v0, v1);
    #pragma unroll
    for (int o = 16; o > 0; o >>= 1)
        m = fmaxf(m, __shfl_xor_sync(0xffffffffu, m, o));
    if (lane == 0) sm.b.red[warp] = m;
    __syncthreads();
    if (tid == 0) {
        float mm = sm.b.red[0];
        #pragma unroll
        for (int w = 1; w < 8; ++w) mm = fmaxf(mm, sm.b.red[w]);
        sm.b.red[0] = mm;
    }
    __syncthreads();
    m = sm.b.red[0];
    __syncthreads();

    const float e0 = __expf(v0 - m);
    const float e1 = __expf(v1 - m);
    float ssum = e0 + e1;
    #pragma unroll
    for (int o = 16; o > 0; o >>= 1)
        ssum += __shfl_xor_sync(0xffffffffu, ssum, o);
    if (lane == 0) sm.b.red[warp] = ssum;
    __syncthreads();
    if (tid == 0) {
        float tot = sm.b.red[0];
        #pragma unroll
        for (int w = 1; w < 8; ++w) tot += sm.b.red[w];
        sm.b.red[0] = tot;
    }
    __syncthreads();
    const float inv = 1.0f / sm.b.red[0];

    const float p0 = e0 * inv;
    const float p1 = e1 * inv;
    sm.b.score[tid]       = p0;
    sm.b.score[tid + 256] = p1;

    // p_attn written once, never re-read: streaming stores keep L2 for v/s1.
    const size_t pbase = ((size_t)h * L_SEQ + i) * L_SEQ;
    __stcs(&out_p[pbase + tid], p0);
    __stcs(&out_p[pbase + tid + 256], p1);
    __syncthreads();

    // Phase 3: out_i[d] = sum_j p[j] * (v[j,d] + rv[i,j,d]).
    const int gid = (warp << 1) + half;
    const float* vrow = v_g  + (size_t)h * L_SEQ * D_DIM;
    const float* rv   = rv_g + (((size_t)h * L_SEQ + i) * L_SEQ) * D_DIM;

    float4 acc = make_float4(0.f, 0.f, 0.f, 0.f);
    #pragma unroll 4
    for (int j = gid; j < L_SEQ; j += 16) {
        const float  pj  = sm.b.score[j];
        const size_t off = (size_t)j * D_DIM + 4 * hl;
        const float4 vv  = *reinterpret_cast<const float4*>(vrow + off);
        const float4 rr  = __ldcs(reinterpret_cast<const float4*>(rv + off));
        acc.x += pj * (vv.x + rr.x);
        acc.y += pj * (vv.y + rr.y);
        acc.z += pj * (vv.z + rr.z);
        acc.w += pj * (vv.w + rr.w);
    }
    sm.b.acc[gid][hl] = acc;
    __syncthreads();

    if (tid < 16) {
        float4 r = make_float4(0.f, 0.f, 0.f, 0.f);
        #pragma unroll
        for (int gg = 0; gg < 16; ++gg) {
            const float4 a = sm.b.acc[gg][tid];
            r.x += a.x; r.y += a.y; r.z += a.z; r.w += a.w;
        }
        float4* oa = reinterpret_cast<float4*>(out_attn + ((size_t)h * L_SEQ + i) * D_DIM);
        oa[tid] = r;
    }

    // Launch-scope cleanup: last stream CTA resets both counters so every
    // launch (incl. graph replays) starts from a clean state.
    __syncthreads();
    if (tid == 0) {
        const unsigned int r = atomicAdd(&g_b_done, 1u);
        if (r == N_STREAM_CTAS - 1) {
            g_a_done = 0;
            g_b_done = 0;
            __threadfence();
        }
    }
}

extern "C" void kernel_launch(void* const* d_in, const int* in_sizes, int n_in,
                              void* d_out, int out_size)
{
    const float* q    = (const float*)d_in[0];
    const float* k    = (const float*)d_in[1];
    const float* v    = (const float*)d_in[2];
    const float* rk   = (const float*)d_in[3];
    const float* rv   = (const float*)d_in[4];
    const int*   mask = (const int*)  d_in[5];

    float* out      = (float*)d_out;
    float* out_attn = out;                                        // [1,8,512,64]
    float* out_p    = out + (size_t)H_HEADS * L_SEQ * D_DIM;      // [1,8,512,512]

    fused_kernel<<<N_QK_CTAS + N_STREAM_CTAS, 256>>>(q, k, v, rk, rv, mask,
                                                     out_attn, out_p);
}